// round 8
// baseline (speedup 1.0000x reference)
#include <cuda_runtime.h>

#define NN 50000
#define EE 800000
#define EN 850000   // EE + NN (self loops)
#define GG 512
#define NBLK 196    // ceil(NN/256)
#define GTB  782    // ceil(NN/64) node tiles for GEMM

// ---------------- scratch (static device globals; no allocation) ----------------
__device__ __align__(16) float g_h [NN * 64];
__device__ __align__(16) float g_t [NN * 64];
__device__ __align__(16) float g_xl[NN * 128];
__device__ __align__(16) float g_xr[NN * 128];
__device__ int   g_deg[NN];
__device__ int   g_rowoff[NN + 1];
__device__ int   g_cursor[NN];
__device__ int   g_csrsrc[EN];
__device__ int   g_bsum[256];

// packed f32x2 FMA: d.lo += a.lo*b.lo ; d.hi += a.hi*b.hi
#define FMA2(d, a, b) asm("fma.rn.f32x2 %0, %1, %2, %0;" : "+l"(d) : "l"(a), "l"(b))

__device__ __forceinline__ float lo_f(unsigned long long v) {
    return __uint_as_float((unsigned)v);
}
__device__ __forceinline__ float hi_f(unsigned long long v) {
    return __uint_as_float((unsigned)(v >> 32));
}

// ---------------- embedding gather (+ deg init fused) ----------------
__global__ void embed_k(const int* __restrict__ x, const float* __restrict__ embed) {
    int t = blockIdx.x * blockDim.x + threadIdx.x;
    if (t >= NN * 16) return;
    int n = t >> 4, q = t & 15;
    if (q == 0) g_deg[n] = 1;     // self loop seed for CSR histogram
    int row = x[n];
    float4 v = *(const float4*)(embed + row * 64 + q * 4);
    *(float4*)(g_h + n * 64 + q * 4) = v;
}

// ---------------- CSR build ----------------
__global__ void hist_k(const int* __restrict__ ei) {
    int e = blockIdx.x * blockDim.x + threadIdx.x;
    if (e >= EE) return;
    atomicAdd(&g_deg[ei[EE + e]], 1);
}

__global__ void blocksum_k() {
    __shared__ int sh[8];
    int i = blockIdx.x * 256 + threadIdx.x;
    int v = (i < NN) ? g_deg[i] : 0;
#pragma unroll
    for (int o = 16; o; o >>= 1) v += __shfl_down_sync(0xffffffffu, v, o);
    if ((threadIdx.x & 31) == 0) sh[threadIdx.x >> 5] = v;
    __syncthreads();
    if (threadIdx.x == 0) {
        int s = 0;
#pragma unroll
        for (int w = 0; w < 8; w++) s += sh[w];
        g_bsum[blockIdx.x] = s;
    }
}

__global__ void bscan_k() {
    __shared__ int sh[256];
    int t = threadIdx.x;
    int v = (t < NBLK) ? g_bsum[t] : 0;
    sh[t] = v;
    __syncthreads();
#pragma unroll
    for (int off = 1; off < 256; off <<= 1) {
        int add = (t >= off) ? sh[t - off] : 0;
        __syncthreads();
        sh[t] += add;
        __syncthreads();
    }
    if (t < NBLK) g_bsum[t] = (t == 0) ? 0 : sh[t - 1];
    if (t == 0) g_rowoff[NN] = EN;
}

__global__ void scatter_scan_k() {
    __shared__ int sh[256];
    int t = threadIdx.x;
    int i = blockIdx.x * 256 + t;
    int v = (i < NN) ? g_deg[i] : 0;
    sh[t] = v;
    __syncthreads();
#pragma unroll
    for (int off = 1; off < 256; off <<= 1) {
        int add = (t >= off) ? sh[t - off] : 0;
        __syncthreads();
        sh[t] += add;
        __syncthreads();
    }
    int excl = ((t == 0) ? 0 : sh[t - 1]) + g_bsum[blockIdx.x];
    if (i < NN) { g_rowoff[i] = excl; g_cursor[i] = excl; }
}

__global__ void fill_k(const int* __restrict__ ei) {
    int t = blockIdx.x * blockDim.x + threadIdx.x;
    if (t >= EN) return;
    int s, d;
    if (t < EE) { s = ei[t]; d = ei[EE + t]; }
    else        { s = t - EE; d = s; }         // self loop
    int pos = atomicAdd(&g_cursor[d], 1);
    g_csrsrc[pos] = s;
}

// ---------------- high-occupancy f32x2 GEMM ----------------
// C[N x KOUT] = act(A[N x 64] @ W[64 x KOUT] + b)
// grid = (782, KOUT/64). Block: 256 threads covering 64 nodes x 64 cols.
// Thread tile 4 nodes x 4 cols (16 ull acc = 32 regs). smem 32KB.
// Per warp per j2: A 2x broadcast LDS.128 (2 wf) + W 2x LDS.128 (4 wf) = 6 wf
// vs 16 FMA2 (32 SMSP-cyc). ~60 regs -> 4 blocks/SM = 32 warps.
template<int KOUT, bool RELU>
__global__ __launch_bounds__(256)
void gemmH_k(const float* __restrict__ A, const float* __restrict__ W,
             const float* __restrict__ bias, float* __restrict__ C) {
    __shared__ __align__(16) float At[32 * 128];   // [j2][node*2 floats] 16KB
    __shared__ __align__(16) float Wp[32 * 128];   // [j2][col*2  floats] 16KB

    int tid = threadIdx.x;          // 0..255
    int n0  = blockIdx.x * 64;
    int c0  = blockIdx.y * 64;

    // stage A transposed: thread t handles node (t&63), col segment (t>>6)*16
    {
        int n   = tid & 63;
        int seg = tid >> 6;                  // 0..3 -> cols seg*16..seg*16+15
        bool v = (n0 + n) < NN;
        const float* arow = A + (n0 + n) * 64 + seg * 16;
#pragma unroll
        for (int it = 0; it < 4; it++) {
            float4 q = v ? *(const float4*)(arow + it * 4)
                         : make_float4(0.f, 0.f, 0.f, 0.f);
            int j2 = seg * 8 + it * 2;
            *(float2*)(At + (j2 + 0) * 128 + n * 2) = make_float2(q.x, q.y);
            *(float2*)(At + (j2 + 1) * 128 + n * 2) = make_float2(q.z, q.w);
        }
    }
    // stage W 64-col slice packed: Wp[j2][c] pair = (W[2j2][c0+c], W[2j2+1][c0+c])
#pragma unroll
    for (int f = tid; f < 64 * 64; f += 256) {
        int j = f >> 6, c = f & 63;
        Wp[((j >> 1) * 128) + c * 2 + (j & 1)] = W[j * KOUT + c0 + c];
    }
    __syncthreads();

    int cg = tid & 15;         // 16 col groups  x 4 cols
    int ng = tid >> 4;         // 16 node groups x 4 nodes

    unsigned long long acc[4][4];
#pragma unroll
    for (int i = 0; i < 4; i++)
#pragma unroll
        for (int c = 0; c < 4; c++) acc[i][c] = 0ull;

    const ulonglong2* A2 = (const ulonglong2*)At;   // row stride 32 ull2
    const ulonglong2* W2 = (const ulonglong2*)Wp;   // row stride 32 ull2

#pragma unroll
    for (int j2 = 0; j2 < 32; j2++) {
        ulonglong2 av0 = A2[j2 * 32 + ng * 2 + 0];   // nodes 4ng, 4ng+1
        ulonglong2 av1 = A2[j2 * 32 + ng * 2 + 1];   // nodes 4ng+2, 4ng+3
        ulonglong2 wv0 = W2[j2 * 32 + cg * 2 + 0];   // cols 4cg, 4cg+1
        ulonglong2 wv1 = W2[j2 * 32 + cg * 2 + 1];   // cols 4cg+2, 4cg+3
        unsigned long long a[4] = {av0.x, av0.y, av1.x, av1.y};
        unsigned long long w[4] = {wv0.x, wv0.y, wv1.x, wv1.y};
#pragma unroll
        for (int i = 0; i < 4; i++)
#pragma unroll
            for (int c = 0; c < 4; c++)
                FMA2(acc[i][c], a[i], w[c]);
    }

    float4 b4 = __ldg((const float4*)(bias + c0 + cg * 4));

#pragma unroll
    for (int i = 0; i < 4; i++) {
        int n = n0 + ng * 4 + i;
        if (n < NN) {
            float4 o;
            o.x = lo_f(acc[i][0]) + hi_f(acc[i][0]) + b4.x;
            o.y = lo_f(acc[i][1]) + hi_f(acc[i][1]) + b4.y;
            o.z = lo_f(acc[i][2]) + hi_f(acc[i][2]) + b4.z;
            o.w = lo_f(acc[i][3]) + hi_f(acc[i][3]) + b4.w;
            if (RELU) {
                o.x = fmaxf(o.x, 0.f); o.y = fmaxf(o.y, 0.f);
                o.z = fmaxf(o.z, 0.f); o.w = fmaxf(o.w, 0.f);
            }
            *(float4*)(C + n * KOUT + c0 + cg * 4) = o;
        }
    }
}

// ---------------- GATv2: one warp per dst, 4-edge batched online softmax ----------------
__global__ void gat_k(const float* __restrict__ xl, const float* __restrict__ xr,
                      const float* __restrict__ att, const float* __restrict__ bias,
                      float* __restrict__ hout) {
    int gw = (blockIdx.x * blockDim.x + threadIdx.x) >> 5;
    if (gw >= NN) return;
    int lane = threadIdx.x & 31;
    int dst = gw;

    float4 xr4 = *(const float4*)(xr + dst * 128 + lane * 4);
    float4 at4 = *(const float4*)(att + lane * 4);

    int beg = __ldg(g_rowoff + dst), end = __ldg(g_rowoff + dst + 1);

    float m = -1e30f, s = 0.f;
    float ax = 0.f, ay = 0.f, az = 0.f, aw = 0.f;

    for (int i = beg; i < end; i += 4) {
        float p[4];
        float4 xs[4];
#pragma unroll
        for (int k = 0; k < 4; k++) {
            bool valid = (i + k) < end;
            int src = valid ? __ldg(g_csrsrc + i + k) : 0;
            xs[k] = __ldg((const float4*)(xl + src * 128 + lane * 4));
            float vx = xs[k].x + xr4.x, vy = xs[k].y + xr4.y;
            float vz = xs[k].z + xr4.z, vw = xs[k].w + xr4.w;
            vx = vx > 0.f ? vx : 0.2f * vx;
            vy = vy > 0.f ? vy : 0.2f * vy;
            vz = vz > 0.f ? vz : 0.2f * vz;
            vw = vw > 0.f ? vw : 0.2f * vw;
            float pk = vx * at4.x + vy * at4.y + vz * at4.z + vw * at4.w;
            p[k] = valid ? pk : -1e30f;
        }
#pragma unroll
        for (int k = 0; k < 4; k++) {
            float pk = p[k];
            pk += __shfl_xor_sync(0xffffffffu, pk, 1);
            pk += __shfl_xor_sync(0xffffffffu, pk, 2);
            pk += __shfl_xor_sync(0xffffffffu, pk, 4);
            pk += __shfl_xor_sync(0xffffffffu, pk, 8);
            p[k] = ((i + k) < end) ? pk : -1e30f;
        }
        float mb = fmaxf(fmaxf(p[0], p[1]), fmaxf(p[2], p[3]));
        float mn = fmaxf(m, mb);
        float r  = __expf(m - mn);
        float w0 = __expf(p[0] - mn);
        float w1 = __expf(p[1] - mn);
        float w2 = __expf(p[2] - mn);
        float w3 = __expf(p[3] - mn);
        s  = s * r + ((w0 + w1) + (w2 + w3));
        ax = ax * r + w0 * xs[0].x + w1 * xs[1].x + w2 * xs[2].x + w3 * xs[3].x;
        ay = ay * r + w0 * xs[0].y + w1 * xs[1].y + w2 * xs[2].y + w3 * xs[3].y;
        az = az * r + w0 * xs[0].z + w1 * xs[1].z + w2 * xs[2].z + w3 * xs[3].z;
        aw = aw * r + w0 * xs[0].w + w1 * xs[1].w + w2 * xs[2].w + w3 * xs[3].w;
        m = mn;
    }

    float inv = 1.f / s;
    ax *= inv; ay *= inv; az *= inv; aw *= inv;

    float bx = ax + __shfl_xor_sync(0xffffffffu, ax, 16);
    float by = ay + __shfl_xor_sync(0xffffffffu, ay, 16);
    float bz = az + __shfl_xor_sync(0xffffffffu, az, 16);
    float bw = aw + __shfl_xor_sync(0xffffffffu, aw, 16);

    if (lane < 16) {
        float4 b4 = *(const float4*)(bias + lane * 4);
        float4 o = make_float4(0.5f * bx + b4.x, 0.5f * by + b4.y,
                               0.5f * bz + b4.z, 0.5f * bw + b4.w);
        *(float4*)(hout + dst * 64 + lane * 4) = o;
    }
}

// ---------------- output zero + graph segment-sum ----------------
__global__ void zero_k(float* __restrict__ out) {
    int t = blockIdx.x * blockDim.x + threadIdx.x;
    if (t < GG * 128 / 4)
        *(float4*)(out + t * 4) = make_float4(0.f, 0.f, 0.f, 0.f);
}

__global__ void segsum_k(const int* __restrict__ batch, const float* __restrict__ outn,
                         float* __restrict__ out) {
    int t = blockIdx.x * blockDim.x + threadIdx.x;
    if (t >= NN * 32) return;
    int n = t >> 5, q = t & 31;
    float4 v = *(const float4*)(outn + n * 128 + q * 4);
    int g = batch[n];
    float* p = out + g * 128 + q * 4;
    atomicAdd(p + 0, v.x);
    atomicAdd(p + 1, v.y);
    atomicAdd(p + 2, v.z);
    atomicAdd(p + 3, v.w);
}

// ---------------- launcher ----------------
extern "C" void kernel_launch(void* const* d_in, const int* in_sizes, int n_in,
                              void* d_out, int out_size) {
    const int* x     = (const int*)d_in[0];
    const int* ei    = (const int*)d_in[1];
    const int* batch = (const int*)d_in[2];
    int base = (in_sizes[3] == 1) ? 4 : 3;
    const float* embed = (const float*)d_in[base + 0];
    const float* lin_W = (const float*)d_in[base + 1];
    const float* lin_b = (const float*)d_in[base + 2];
    const float* gWl   = (const float*)d_in[base + 3];
    const float* gbl   = (const float*)d_in[base + 4];
    const float* gWr   = (const float*)d_in[base + 5];
    const float* gbr   = (const float*)d_in[base + 6];
    const float* gatt  = (const float*)d_in[base + 7];
    const float* gbias = (const float*)d_in[base + 8];
    const float* rW    = (const float*)d_in[base + 9];
    const float* rb    = (const float*)d_in[base + 10];
    float* out = (float*)d_out;

    void *ph, *pt, *pxl, *pxr;
    cudaGetSymbolAddress(&ph,  g_h);
    cudaGetSymbolAddress(&pt,  g_t);
    cudaGetSymbolAddress(&pxl, g_xl);
    cudaGetSymbolAddress(&pxr, g_xr);
    float* h  = (float*)ph;
    float* tb = (float*)pt;
    float* xl = (float*)pxl;
    float* xr = (float*)pxr;

    dim3 g64(GTB, 1), g128(GTB, 2);

    // launches 1-2
    embed_k<<<(NN * 16 + 255) / 256, 256>>>(x, embed);   // also inits g_deg
    hist_k<<<(EE + 255) / 256, 256>>>(ei);

    // launch 3 = lin, launch 4 = xl GEMM (ncu capture slot)
    gemmH_k<64, true><<<g64, 256>>>(h, lin_W, lin_b, tb);
    gemmH_k<128, false><<<g128, 256>>>(tb, gWl, gbl, xl);
    gemmH_k<128, false><<<g128, 256>>>(tb, gWr, gbr, xr);

    // finish CSR build (needed only by gat_k)
    blocksum_k<<<NBLK, 256>>>();
    bscan_k<<<1, 256>>>();
    scatter_scan_k<<<NBLK, 256>>>();
    fill_k<<<(EN + 255) / 256, 256>>>(ei);

    gat_k<<<(NN + 7) / 8, 256>>>(xl, xr, gatt, gbias, h);

    for (int l = 1; l < 3; l++) {
        gemmH_k<64, true><<<g64, 256>>>(h, lin_W + l * 64 * 64, lin_b + l * 64, tb);
        gemmH_k<128, false><<<g128, 256>>>(tb, gWl + l * 64 * 128, gbl + l * 128, xl);
        gemmH_k<128, false><<<g128, 256>>>(tb, gWr + l * 64 * 128, gbr + l * 128, xr);
        gat_k<<<(NN + 7) / 8, 256>>>(xl, xr, gatt + l * 128, gbias + l * 64, h);
    }

    gemmH_k<128, false><<<g128, 256>>>(h, rW, rb, xl);
    zero_k<<<(GG * 128 / 4 + 255) / 256, 256>>>(out);
    segsum_k<<<(NN * 32 + 255) / 256, 256>>>(batch, xl, out);
}

// round 12
// speedup vs baseline: 2.1041x; 2.1041x over previous
#include <cuda_runtime.h>
#include <cuda.h>
#include <cstdint>
#include <cstddef>

#define NN 50000
#define EE 800000
#define EN 850000   // EE + NN (self loops)
#define GG 512
#define NBLK 196    // ceil(NN/256)
#define GTB  391    // ceil(NN/128) node tiles for tensor GEMM

// ---------------- scratch (static device globals; no allocation) ----------------
__device__ __align__(16) float g_h [NN * 64];
__device__ __align__(16) float g_t [NN * 64];
__device__ __align__(16) float g_xl[NN * 128];
__device__ __align__(16) float g_xr[NN * 128];
__device__ int   g_deg[NN];
__device__ int   g_rowoff[NN + 1];
__device__ int   g_cursor[NN];
__device__ int   g_csrsrc[EN];
__device__ int   g_bsum[256];

// ---------------- helpers ----------------
__device__ __forceinline__ uint32_t smem_to_u32(const void* smem_ptr) {
    uint32_t addr;
    asm("{ .reg .u64 tmp; cvta.to.shared.u64 tmp, %1; cvt.u32.u64 %0, tmp; }"
        : "=r"(addr) : "l"(smem_ptr));
    return addr;
}

#define SMEM_SWIZZLE_128B(byte_offset) \
    ((byte_offset) ^ (((byte_offset) >> 3) & 0x70))

// pack two floats to bf16x2 (first arg -> LOW half = lower k index)
__device__ __forceinline__ uint32_t bf2(float lo, float hi) {
    uint32_t r;
    asm("cvt.rn.bf16x2.f32 %0, %1, %2;" : "=r"(r) : "f"(hi), "f"(lo));
    return r;
}
__device__ __forceinline__ float bflo(uint32_t p) { return __uint_as_float(p << 16); }
__device__ __forceinline__ float bfhi(uint32_t p) { return __uint_as_float(p & 0xffff0000u); }

// ldmatrix: 8x8 b16 tiles from shared memory (sm_75+ baseline PTX)
__device__ __forceinline__ void ldm_x4(uint32_t* r, uint32_t addr) {
    asm volatile("ldmatrix.sync.aligned.m8n8.x4.shared.b16 {%0,%1,%2,%3}, [%4];"
        : "=r"(r[0]), "=r"(r[1]), "=r"(r[2]), "=r"(r[3]) : "r"(addr));
}
__device__ __forceinline__ void ldm_x2(uint32_t* r, uint32_t addr) {
    asm volatile("ldmatrix.sync.aligned.m8n8.x2.shared.b16 {%0,%1}, [%2];"
        : "=r"(r[0]), "=r"(r[1]) : "r"(addr));
}

// warp-level bf16 MMA with fp32 accumulate (sm_80+ baseline PTX)
__device__ __forceinline__ void mma_bf16(float* d, const uint32_t* a, const uint32_t* b) {
    asm volatile(
        "mma.sync.aligned.m16n8k16.row.col.f32.bf16.bf16.f32 "
        "{%0,%1,%2,%3}, {%4,%5,%6,%7}, {%8,%9}, {%0,%1,%2,%3};"
        : "+f"(d[0]), "+f"(d[1]), "+f"(d[2]), "+f"(d[3])
        : "r"(a[0]), "r"(a[1]), "r"(a[2]), "r"(a[3]), "r"(b[0]), "r"(b[1]));
}

// ---------------- embedding gather (+ deg init fused) ----------------
__global__ void embed_k(const int* __restrict__ x, const float* __restrict__ embed) {
    int t = blockIdx.x * blockDim.x + threadIdx.x;
    if (t >= NN * 16) return;
    int n = t >> 4, q = t & 15;
    if (q == 0) g_deg[n] = 1;
    int row = x[n];
    float4 v = *(const float4*)(embed + row * 64 + q * 4);
    *(float4*)(g_h + n * 64 + q * 4) = v;
}

// ---------------- CSR build ----------------
__global__ void hist_k(const int* __restrict__ ei) {
    int e = blockIdx.x * blockDim.x + threadIdx.x;
    if (e >= EE) return;
    atomicAdd(&g_deg[ei[EE + e]], 1);
}

__global__ void blocksum_k() {
    __shared__ int sh[8];
    int i = blockIdx.x * 256 + threadIdx.x;
    int v = (i < NN) ? g_deg[i] : 0;
#pragma unroll
    for (int o = 16; o; o >>= 1) v += __shfl_down_sync(0xffffffffu, v, o);
    if ((threadIdx.x & 31) == 0) sh[threadIdx.x >> 5] = v;
    __syncthreads();
    if (threadIdx.x == 0) {
        int s = 0;
#pragma unroll
        for (int w = 0; w < 8; w++) s += sh[w];
        g_bsum[blockIdx.x] = s;
    }
}

__global__ void bscan_k() {
    __shared__ int sh[256];
    int t = threadIdx.x;
    int v = (t < NBLK) ? g_bsum[t] : 0;
    sh[t] = v;
    __syncthreads();
#pragma unroll
    for (int off = 1; off < 256; off <<= 1) {
        int add = (t >= off) ? sh[t - off] : 0;
        __syncthreads();
        sh[t] += add;
        __syncthreads();
    }
    if (t < NBLK) g_bsum[t] = (t == 0) ? 0 : sh[t - 1];
    if (t == 0) g_rowoff[NN] = EN;
}

__global__ void scatter_scan_k() {
    __shared__ int sh[256];
    int t = threadIdx.x;
    int i = blockIdx.x * 256 + t;
    int v = (i < NN) ? g_deg[i] : 0;
    sh[t] = v;
    __syncthreads();
#pragma unroll
    for (int off = 1; off < 256; off <<= 1) {
        int add = (t >= off) ? sh[t - off] : 0;
        __syncthreads();
        sh[t] += add;
        __syncthreads();
    }
    int excl = ((t == 0) ? 0 : sh[t - 1]) + g_bsum[blockIdx.x];
    if (i < NN) { g_rowoff[i] = excl; g_cursor[i] = excl; }
}

__global__ void fill_k(const int* __restrict__ ei) {
    int t = blockIdx.x * blockDim.x + threadIdx.x;
    if (t >= EN) return;
    int s, d;
    if (t < EE) { s = ei[t]; d = ei[EE + t]; }
    else        { s = t - EE; d = s; }
    int pos = atomicAdd(&g_cursor[d], 1);
    g_csrsrc[pos] = s;
}

// ---------------- mma.sync split-bf16 GEMM ----------------
// C[N x KOUT] = act(A[N x 64] @ W[64 x KOUT] + b), fp32 in/out.
// Block: 256 threads (8 warps), tile = 128 nodes x KOUT cols.
// A = Ah+Al, W = Wh+Wl (bf16 hi/lo split): D = Ah*Wh + Ah*Wl + Al*Wh (fp32 acc).
// Staging: A[128 rows][64 k] and Bt[KOUT rows][64 k] bf16, 128B rows, SW128 swizzle.
// Warp w computes rows [w*16, w*16+16): per k-step ldmatrix.x4 A frags, per 8-col
// tile ldmatrix.x2 B frags (Bt row-major [n][k] == col-major B fragment), 3 MMAs.
template<int KOUT, bool RELU>
__global__ void __launch_bounds__(256) gemmM_k(
    const float* __restrict__ A, const float* __restrict__ W,
    const float* __restrict__ bias, float* __restrict__ C) {
    extern __shared__ __align__(1024) char smem[];
    const int SM_AH = 0;
    const int SM_AL = 16384;                  // A: 128 rows x 128B
    const int SM_BH = 32768;
    const int SM_BL = 32768 + KOUT * 128;     // B: KOUT rows x 128B
    constexpr int NT = KOUT / 8;              // 8-col tiles per warp

    uint32_t sb = smem_to_u32(smem);
    int tid  = threadIdx.x;                   // 0..255
    int wid  = tid >> 5;
    int lane = tid & 31;
    int n0   = blockIdx.x * 128;

    // ---- stage A hi/lo: two threads per node row, 8 float4 each ----
    {
        int n    = tid & 127;
        int half = tid >> 7;
        bool valid = (n0 + n) < NN;
        const float4* ar = (const float4*)(A + (size_t)(n0 + n) * 64);
        uint32_t rowoff = (uint32_t)n * 128;
#pragma unroll
        for (int q = half * 8; q < half * 8 + 8; q += 2) {
            float4 f0 = valid ? __ldg(ar + q)     : make_float4(0.f, 0.f, 0.f, 0.f);
            float4 f1 = valid ? __ldg(ar + q + 1) : make_float4(0.f, 0.f, 0.f, 0.f);
            uint32_t h0 = bf2(f0.x, f0.y);
            uint32_t h1 = bf2(f0.z, f0.w);
            uint32_t h2 = bf2(f1.x, f1.y);
            uint32_t h3 = bf2(f1.z, f1.w);
            uint32_t l0 = bf2(f0.x - bflo(h0), f0.y - bfhi(h0));
            uint32_t l1 = bf2(f0.z - bflo(h1), f0.w - bfhi(h1));
            uint32_t l2 = bf2(f1.x - bflo(h2), f1.y - bfhi(h2));
            uint32_t l3 = bf2(f1.z - bflo(h3), f1.w - bfhi(h3));
            uint32_t off = SMEM_SWIZZLE_128B(rowoff + (uint32_t)q * 8);   // 16B aligned
            *(uint4*)(smem + SM_AH + off) = make_uint4(h0, h1, h2, h3);
            *(uint4*)(smem + SM_AL + off) = make_uint4(l0, l1, l2, l3);
        }
    }
    // ---- stage Bt hi/lo: row c = output col, k contiguous ----
    {
        constexpr int NPAIRS = 32 * KOUT;           // k-pairs x cols
#pragma unroll
        for (int pf = tid; pf < NPAIRS; pf += 256) {
            int j2 = pf / KOUT;
            int c  = pf % KOUT;
            float w0 = __ldg(W + (size_t)(2 * j2)     * KOUT + c);
            float w1 = __ldg(W + (size_t)(2 * j2 + 1) * KOUT + c);
            uint32_t hp = bf2(w0, w1);
            uint32_t lp = bf2(w0 - bflo(hp), w1 - bfhi(hp));
            uint32_t off = SMEM_SWIZZLE_128B((uint32_t)c * 128 + (uint32_t)j2 * 4);
            *(uint32_t*)(smem + SM_BH + off) = hp;
            *(uint32_t*)(smem + SM_BL + off) = lp;
        }
    }
    __syncthreads();

    // ---- MMA mainloop ----
    float acc[NT][4];
#pragma unroll
    for (int t = 0; t < NT; t++) {
        acc[t][0] = 0.f; acc[t][1] = 0.f; acc[t][2] = 0.f; acc[t][3] = 0.f;
    }

    // per-lane ldmatrix source addresses (swizzled)
    uint32_t a_row   = (uint32_t)(wid * 16 + (lane & 15));
    uint32_t a_sel   = (uint32_t)(lane >> 4);            // 0: k0-7, 1: k8-15 chunk pair
    uint32_t b_row_l = (uint32_t)(lane & 7);
    uint32_t b_sel   = (uint32_t)((lane >> 3) & 1);

#pragma unroll
    for (int ks = 0; ks < 4; ks++) {
        uint32_t ah[4], al[4];
        uint32_t aoff = SMEM_SWIZZLE_128B(a_row * 128 + (uint32_t)(ks * 2 + a_sel) * 16);
        ldm_x4(ah, sb + SM_AH + aoff);
        ldm_x4(al, sb + SM_AL + aoff);
#pragma unroll
        for (int t = 0; t < NT; t++) {
            uint32_t bh[2], bl[2];
            uint32_t boff = SMEM_SWIZZLE_128B(((uint32_t)(t * 8) + b_row_l) * 128 +
                                              (uint32_t)(ks * 2 + b_sel) * 16);
            ldm_x2(bh, sb + SM_BH + boff);
            ldm_x2(bl, sb + SM_BL + boff);
            mma_bf16(acc[t], ah, bh);
            mma_bf16(acc[t], ah, bl);
            mma_bf16(acc[t], al, bh);
        }
    }

    // ---- epilogue: lane l holds rows (w*16 + l>>2) and (+8), cols 2(l&3), 2(l&3)+1 ----
    {
        int r0 = n0 + wid * 16 + (lane >> 2);
        int r1 = r0 + 8;
#pragma unroll
        for (int t = 0; t < NT; t++) {
            int c = t * 8 + 2 * (lane & 3);
            float2 bb = *(const float2*)(bias + c);
            float2 o0 = make_float2(acc[t][0] + bb.x, acc[t][1] + bb.y);
            float2 o1 = make_float2(acc[t][2] + bb.x, acc[t][3] + bb.y);
            if (RELU) {
                o0.x = fmaxf(o0.x, 0.f); o0.y = fmaxf(o0.y, 0.f);
                o1.x = fmaxf(o1.x, 0.f); o1.y = fmaxf(o1.y, 0.f);
            }
            if (r0 < NN) *(float2*)(C + (size_t)r0 * KOUT + c) = o0;
            if (r1 < NN) *(float2*)(C + (size_t)r1 * KOUT + c) = o1;
        }
    }
}

// ---------------- GATv2: one warp per dst, 4-edge batched online softmax ----------------
__global__ void gat_k(const float* __restrict__ xl, const float* __restrict__ xr,
                      const float* __restrict__ att, const float* __restrict__ bias,
                      float* __restrict__ hout) {
    int gw = (blockIdx.x * blockDim.x + threadIdx.x) >> 5;
    if (gw >= NN) return;
    int lane = threadIdx.x & 31;
    int dst = gw;

    float4 xr4 = *(const float4*)(xr + dst * 128 + lane * 4);
    float4 at4 = *(const float4*)(att + lane * 4);

    int beg = __ldg(g_rowoff + dst), end = __ldg(g_rowoff + dst + 1);

    float m = -1e30f, s = 0.f;
    float ax = 0.f, ay = 0.f, az = 0.f, aw = 0.f;

    for (int i = beg; i < end; i += 4) {
        float p[4];
        float4 xs[4];
#pragma unroll
        for (int k = 0; k < 4; k++) {
            bool valid = (i + k) < end;
            int src = valid ? __ldg(g_csrsrc + i + k) : 0;
            xs[k] = __ldg((const float4*)(xl + src * 128 + lane * 4));
            float vx = xs[k].x + xr4.x, vy = xs[k].y + xr4.y;
            float vz = xs[k].z + xr4.z, vw = xs[k].w + xr4.w;
            vx = vx > 0.f ? vx : 0.2f * vx;
            vy = vy > 0.f ? vy : 0.2f * vy;
            vz = vz > 0.f ? vz : 0.2f * vz;
            vw = vw > 0.f ? vw : 0.2f * vw;
            float pk = vx * at4.x + vy * at4.y + vz * at4.z + vw * at4.w;
            p[k] = valid ? pk : -1e30f;
        }
#pragma unroll
        for (int k = 0; k < 4; k++) {
            float pk = p[k];
            pk += __shfl_xor_sync(0xffffffffu, pk, 1);
            pk += __shfl_xor_sync(0xffffffffu, pk, 2);
            pk += __shfl_xor_sync(0xffffffffu, pk, 4);
            pk += __shfl_xor_sync(0xffffffffu, pk, 8);
            p[k] = ((i + k) < end) ? pk : -1e30f;
        }
        float mb = fmaxf(fmaxf(p[0], p[1]), fmaxf(p[2], p[3]));
        float mn = fmaxf(m, mb);
        float r  = __expf(m - mn);
        float w0 = __expf(p[0] - mn);
        float w1 = __expf(p[1] - mn);
        float w2 = __expf(p[2] - mn);
        float w3 = __expf(p[3] - mn);
        s  = s * r + ((w0 + w1) + (w2 + w3));
        ax = ax * r + w0 * xs[0].x + w1 * xs[1].x + w2 * xs[2].x + w3 * xs[3].x;
        ay = ay * r + w0 * xs[0].y + w1 * xs[1].y + w2 * xs[2].y + w3 * xs[3].y;
        az = az * r + w0 * xs[0].z + w1 * xs[1].z + w2 * xs[2].z + w3 * xs[3].z;
        aw = aw * r + w0 * xs[0].w + w1 * xs[1].w + w2 * xs[2].w + w3 * xs[3].w;
        m = mn;
    }

    float inv = 1.f / s;
    ax *= inv; ay *= inv; az *= inv; aw *= inv;

    float bx = ax + __shfl_xor_sync(0xffffffffu, ax, 16);
    float by = ay + __shfl_xor_sync(0xffffffffu, ay, 16);
    float bz = az + __shfl_xor_sync(0xffffffffu, az, 16);
    float bw = aw + __shfl_xor_sync(0xffffffffu, aw, 16);

    if (lane < 16) {
        float4 b4 = *(const float4*)(bias + lane * 4);
        float4 o = make_float4(0.5f * bx + b4.x, 0.5f * by + b4.y,
                               0.5f * bz + b4.z, 0.5f * bw + b4.w);
        *(float4*)(hout + dst * 64 + lane * 4) = o;
    }
}

// ---------------- output zero + graph segment-sum ----------------
__global__ void zero_k(float* __restrict__ out) {
    int t = blockIdx.x * blockDim.x + threadIdx.x;
    if (t < GG * 128 / 4)
        *(float4*)(out + t * 4) = make_float4(0.f, 0.f, 0.f, 0.f);
}

__global__ void segsum_k(const int* __restrict__ batch, const float* __restrict__ outn,
                         float* __restrict__ out) {
    int t = blockIdx.x * blockDim.x + threadIdx.x;
    if (t >= NN * 32) return;
    int n = t >> 5, q = t & 31;
    float4 v = *(const float4*)(outn + n * 128 + q * 4);
    int g = batch[n];
    float* p = out + g * 128 + q * 4;
    atomicAdd(p + 0, v.x);
    atomicAdd(p + 1, v.y);
    atomicAdd(p + 2, v.z);
    atomicAdd(p + 3, v.w);
}

// ---------------- launcher ----------------
extern "C" void kernel_launch(void* const* d_in, const int* in_sizes, int n_in,
                              void* d_out, int out_size) {
    const int* x     = (const int*)d_in[0];
    const int* ei    = (const int*)d_in[1];
    const int* batch = (const int*)d_in[2];
    int base = (in_sizes[3] == 1) ? 4 : 3;
    const float* embed = (const float*)d_in[base + 0];
    const float* lin_W = (const float*)d_in[base + 1];
    const float* lin_b = (const float*)d_in[base + 2];
    const float* gWl   = (const float*)d_in[base + 3];
    const float* gbl   = (const float*)d_in[base + 4];
    const float* gWr   = (const float*)d_in[base + 5];
    const float* gbr   = (const float*)d_in[base + 6];
    const float* gatt  = (const float*)d_in[base + 7];
    const float* gbias = (const float*)d_in[base + 8];
    const float* rW    = (const float*)d_in[base + 9];
    const float* rb    = (const float*)d_in[base + 10];
    float* out = (float*)d_out;

    void* ph  = 0;
    void* pt  = 0;
    void* pxl = 0;
    void* pxr = 0;
    cudaGetSymbolAddress(&ph,  g_h);
    cudaGetSymbolAddress(&pt,  g_t);
    cudaGetSymbolAddress(&pxl, g_xl);
    cudaGetSymbolAddress(&pxr, g_xr);
    float* h  = (float*)ph;
    float* tb = (float*)pt;
    float* xl = (float*)pxl;
    float* xr = (float*)pxr;

    const int SMEM64  = 32768 + 64  * 256;   // 49152
    const int SMEM128 = 32768 + 128 * 256;   // 65536
    cudaFuncSetAttribute(gemmM_k<64,  true >, cudaFuncAttributeMaxDynamicSharedMemorySize, SMEM64);
    cudaFuncSetAttribute(gemmM_k<128, false>, cudaFuncAttributeMaxDynamicSharedMemorySize, SMEM128);

    // launches 1-2
    embed_k<<<(NN * 16 + 255) / 256, 256>>>(x, embed);   // also inits g_deg
    hist_k<<<(EE + 255) / 256, 256>>>(ei);

    // layer 0 GEMMs (ncu capture slot lands on a tensor GEMM)
    gemmM_k<64,  true ><<<GTB, 256, SMEM64 >>>(h,  lin_W, lin_b, tb);
    gemmM_k<128, false><<<GTB, 256, SMEM128>>>(tb, gWl,   gbl,   xl);
    gemmM_k<128, false><<<GTB, 256, SMEM128>>>(tb, gWr,   gbr,   xr);

    // finish CSR build (needed only by gat_k)
    blocksum_k<<<NBLK, 256>>>();
    bscan_k<<<1, 256>>>();
    scatter_scan_k<<<NBLK, 256>>>();
    fill_k<<<(EN + 255) / 256, 256>>>(ei);

    gat_k<<<(NN + 7) / 8, 256>>>(xl, xr, gatt, gbias, h);

    for (int l = 1; l < 3; l++) {
        gemmM_k<64,  true ><<<GTB, 256, SMEM64 >>>(h,  lin_W + l * 64 * 64,  lin_b + l * 64,  tb);
        gemmM_k<128, false><<<GTB, 256, SMEM128>>>(tb, gWl   + l * 64 * 128, gbl   + l * 128, xl);
        gemmM_k<128, false><<<GTB, 256, SMEM128>>>(tb, gWr   + l * 64 * 128, gbr   + l * 128, xr);
        gat_k<<<(NN + 7) / 8, 256>>>(xl, xr, gatt + l * 128, gbias + l * 64, h);
    }

    gemmM_k<128, false><<<GTB, 256, SMEM128>>>(h, rW, rb, xl);
    zero_k<<<(GG * 128 / 4 + 255) / 256, 256>>>(out);
    segsum_k<<<(NN * 32 + 255) / 256, 256>>>(batch, xl, out);
}

// round 13
// speedup vs baseline: 2.3975x; 1.1394x over previous
#include <cuda_runtime.h>
#include <cuda.h>
#include <cstdint>
#include <cstddef>

#define NN 50000
#define EE 800000
#define EN 850000   // EE + NN (self loops)
#define GG 512
#define NBLK 196    // ceil(NN/256)
#define GTB  391    // ceil(NN/128) node tiles for tensor GEMM

// ---------------- scratch (static device globals; no allocation) ----------------
__device__ __align__(16) float g_h [NN * 64];
__device__ __align__(16) float g_xl[NN * 128];
__device__ __align__(16) float g_xr[NN * 128];
__device__ int   g_deg[NN];
__device__ int   g_rowoff[NN + 1];
__device__ int   g_cursor[NN];
__device__ int   g_csrsrc[EN];
__device__ int   g_bsum[256];

// ---------------- helpers ----------------
__device__ __forceinline__ uint32_t smem_to_u32(const void* smem_ptr) {
    uint32_t addr;
    asm("{ .reg .u64 tmp; cvta.to.shared.u64 tmp, %1; cvt.u32.u64 %0, tmp; }"
        : "=r"(addr) : "l"(smem_ptr));
    return addr;
}

#define SMEM_SWIZZLE_128B(byte_offset) \
    ((byte_offset) ^ (((byte_offset) >> 3) & 0x70))

// pack two floats to bf16x2 (first arg -> LOW half = lower index)
__device__ __forceinline__ uint32_t bf2(float lo, float hi) {
    uint32_t r;
    asm("cvt.rn.bf16x2.f32 %0, %1, %2;" : "=r"(r) : "f"(hi), "f"(lo));
    return r;
}
__device__ __forceinline__ float bflo(uint32_t p) { return __uint_as_float(p << 16); }
__device__ __forceinline__ float bfhi(uint32_t p) { return __uint_as_float(p & 0xffff0000u); }

__device__ __forceinline__ void ldm_x4(uint32_t* r, uint32_t addr) {
    asm volatile("ldmatrix.sync.aligned.m8n8.x4.shared.b16 {%0,%1,%2,%3}, [%4];"
        : "=r"(r[0]), "=r"(r[1]), "=r"(r[2]), "=r"(r[3]) : "r"(addr));
}
__device__ __forceinline__ void ldm_x2(uint32_t* r, uint32_t addr) {
    asm volatile("ldmatrix.sync.aligned.m8n8.x2.shared.b16 {%0,%1}, [%2];"
        : "=r"(r[0]), "=r"(r[1]) : "r"(addr));
}
__device__ __forceinline__ void mma_bf16(float* d, const uint32_t* a, const uint32_t* b) {
    asm volatile(
        "mma.sync.aligned.m16n8k16.row.col.f32.bf16.bf16.f32 "
        "{%0,%1,%2,%3}, {%4,%5,%6,%7}, {%8,%9}, {%0,%1,%2,%3};"
        : "+f"(d[0]), "+f"(d[1]), "+f"(d[2]), "+f"(d[3])
        : "r"(a[0]), "r"(a[1]), "r"(a[2]), "r"(a[3]), "r"(b[0]), "r"(b[1]));
}

// split a float pair (adjacent indices) into bf16x2 hi + lo-residual words
__device__ __forceinline__ void split2(float x, float y, uint32_t& hp, uint32_t& lp) {
    hp = bf2(x, y);
    lp = bf2(x - bflo(hp), y - bfhi(hp));
}

// ---------------- embedding gather (+ deg init fused) ----------------
__global__ void embed_k(const int* __restrict__ x, const float* __restrict__ embed) {
    int t = blockIdx.x * blockDim.x + threadIdx.x;
    if (t >= NN * 16) return;
    int n = t >> 4, q = t & 15;
    if (q == 0) g_deg[n] = 1;
    int row = x[n];
    float4 v = *(const float4*)(embed + row * 64 + q * 4);
    *(float4*)(g_h + n * 64 + q * 4) = v;
}

// ---------------- CSR build ----------------
__global__ void hist_k(const int* __restrict__ ei) {
    int e = blockIdx.x * blockDim.x + threadIdx.x;
    if (e >= EE) return;
    atomicAdd(&g_deg[ei[EE + e]], 1);
}

__global__ void blocksum_k() {
    __shared__ int sh[8];
    int i = blockIdx.x * 256 + threadIdx.x;
    int v = (i < NN) ? g_deg[i] : 0;
#pragma unroll
    for (int o = 16; o; o >>= 1) v += __shfl_down_sync(0xffffffffu, v, o);
    if ((threadIdx.x & 31) == 0) sh[threadIdx.x >> 5] = v;
    __syncthreads();
    if (threadIdx.x == 0) {
        int s = 0;
#pragma unroll
        for (int w = 0; w < 8; w++) s += sh[w];
        g_bsum[blockIdx.x] = s;
    }
}

__global__ void bscan_k() {
    __shared__ int sh[256];
    int t = threadIdx.x;
    int v = (t < NBLK) ? g_bsum[t] : 0;
    sh[t] = v;
    __syncthreads();
#pragma unroll
    for (int off = 1; off < 256; off <<= 1) {
        int add = (t >= off) ? sh[t - off] : 0;
        __syncthreads();
        sh[t] += add;
        __syncthreads();
    }
    if (t < NBLK) g_bsum[t] = (t == 0) ? 0 : sh[t - 1];
    if (t == 0) g_rowoff[NN] = EN;
}

__global__ void scatter_scan_k() {
    __shared__ int sh[256];
    int t = threadIdx.x;
    int i = blockIdx.x * 256 + t;
    int v = (i < NN) ? g_deg[i] : 0;
    sh[t] = v;
    __syncthreads();
#pragma unroll
    for (int off = 1; off < 256; off <<= 1) {
        int add = (t >= off) ? sh[t - off] : 0;
        __syncthreads();
        sh[t] += add;
        __syncthreads();
    }
    int excl = ((t == 0) ? 0 : sh[t - 1]) + g_bsum[blockIdx.x];
    if (i < NN) { g_rowoff[i] = excl; g_cursor[i] = excl; }
}

__global__ void fill_k(const int* __restrict__ ei) {
    int t = blockIdx.x * blockDim.x + threadIdx.x;
    if (t >= EN) return;
    int s, d;
    if (t < EE) { s = ei[t]; d = ei[EE + t]; }
    else        { s = t - EE; d = s; }
    int pos = atomicAdd(&g_cursor[d], 1);
    g_csrsrc[pos] = s;
}

// ---------------- fused layer kernel: lin -> (xl, xr) ----------------
// For a 128-node tile:
//   t = relu(h @ linW + lin_b)           [128 x 64]   phase 1 (16 warps, 32-col halves)
//   xl = t @ Wl + bl ; xr = t @ Wr + br  [128 x 128]  phase 2 (warps 0-7 xl, 8-15 xr)
// All operands bf16 hi/lo split (D = Ah*Bh + Ah*Bl + Al*Bh), fp32 accum.
// SW128-swizzled smem tiles, 128B rows.
__global__ void __launch_bounds__(512) fused_layer_k(
    const float* __restrict__ h, const float* __restrict__ linW,
    const float* __restrict__ lin_b, const float* __restrict__ Wl,
    const float* __restrict__ bl, const float* __restrict__ Wr,
    const float* __restrict__ br,
    float* __restrict__ xl, float* __restrict__ xr) {
    extern __shared__ __align__(1024) char smem[];
    const int A_H  = 0,       A_L  = 16384;    // h tile      128x64 bf16
    const int LW_H = 32768,   LW_L = 40960;    // linW        64x64  bf16 (Bt layout)
    const int A2_H = 49152,   A2_L = 65536;    // lin result  128x64 bf16
    const int BL_H = 81920,   BL_L = 98304;    // Wl          128x64 bf16 (Bt layout)
    const int BR_H = 114688,  BR_L = 131072;   // Wr

    uint32_t sb = smem_to_u32(smem);
    int tid  = threadIdx.x;                    // 0..511
    int wid  = tid >> 5;                       // 0..15
    int lane = tid & 31;
    int n0   = blockIdx.x * 128;

    // ---- stage A = h hi/lo ----
    {
        int n  = tid & 127;
        int q4 = tid >> 7;                     // 0..3
        bool valid = (n0 + n) < NN;
        const float4* ar = (const float4*)(h + (size_t)(n0 + n) * 64);
        uint32_t rowoff = (uint32_t)n * 128;
#pragma unroll
        for (int q = q4 * 4; q < q4 * 4 + 4; q += 2) {
            float4 f0 = valid ? __ldg(ar + q)     : make_float4(0.f, 0.f, 0.f, 0.f);
            float4 f1 = valid ? __ldg(ar + q + 1) : make_float4(0.f, 0.f, 0.f, 0.f);
            uint32_t h0, l0, h1, l1, h2, l2, h3, l3;
            split2(f0.x, f0.y, h0, l0);
            split2(f0.z, f0.w, h1, l1);
            split2(f1.x, f1.y, h2, l2);
            split2(f1.z, f1.w, h3, l3);
            uint32_t off = SMEM_SWIZZLE_128B(rowoff + (uint32_t)q * 8);
            *(uint4*)(smem + A_H + off) = make_uint4(h0, h1, h2, h3);
            *(uint4*)(smem + A_L + off) = make_uint4(l0, l1, l2, l3);
        }
    }
    // ---- stage linW hi/lo (Bt layout: row = out col, k contiguous) ----
#pragma unroll
    for (int pf = tid; pf < 32 * 64; pf += 512) {
        int j2 = pf >> 6, c = pf & 63;
        float w0 = __ldg(linW + (size_t)(2 * j2)     * 64 + c);
        float w1 = __ldg(linW + (size_t)(2 * j2 + 1) * 64 + c);
        uint32_t hp, lp;
        split2(w0, w1, hp, lp);
        uint32_t off = SMEM_SWIZZLE_128B((uint32_t)c * 128 + (uint32_t)j2 * 4);
        *(uint32_t*)(smem + LW_H + off) = hp;
        *(uint32_t*)(smem + LW_L + off) = lp;
    }
    // ---- stage Wl, Wr hi/lo ----
#pragma unroll
    for (int pf = tid; pf < 32 * 128; pf += 512) {
        int j2 = pf >> 7, c = pf & 127;
        uint32_t off = SMEM_SWIZZLE_128B((uint32_t)c * 128 + (uint32_t)j2 * 4);
        float w0 = __ldg(Wl + (size_t)(2 * j2)     * 128 + c);
        float w1 = __ldg(Wl + (size_t)(2 * j2 + 1) * 128 + c);
        uint32_t hp, lp;
        split2(w0, w1, hp, lp);
        *(uint32_t*)(smem + BL_H + off) = hp;
        *(uint32_t*)(smem + BL_L + off) = lp;
        w0 = __ldg(Wr + (size_t)(2 * j2)     * 128 + c);
        w1 = __ldg(Wr + (size_t)(2 * j2 + 1) * 128 + c);
        split2(w0, w1, hp, lp);
        *(uint32_t*)(smem + BR_H + off) = hp;
        *(uint32_t*)(smem + BR_L + off) = lp;
    }
    __syncthreads();

    uint32_t a_sel   = (uint32_t)(lane >> 4);
    uint32_t b_row_l = (uint32_t)(lane & 7);
    uint32_t b_sel   = (uint32_t)((lane >> 3) & 1);

    // ---- phase 1: lin tile. warp w: rows (w&7)*16, cols (w>>3)*32 ----
    {
        int rg = (wid & 7) * 16;
        int ch = wid >> 3;
        float acc[4][4];
#pragma unroll
        for (int t = 0; t < 4; t++) {
            acc[t][0] = 0.f; acc[t][1] = 0.f; acc[t][2] = 0.f; acc[t][3] = 0.f;
        }
        uint32_t a_row = (uint32_t)(rg + (lane & 15));
#pragma unroll
        for (int ks = 0; ks < 4; ks++) {
            uint32_t ah[4], al[4];
            uint32_t aoff = SMEM_SWIZZLE_128B(a_row * 128 + (uint32_t)(ks * 2 + a_sel) * 16);
            ldm_x4(ah, sb + A_H + aoff);
            ldm_x4(al, sb + A_L + aoff);
#pragma unroll
            for (int t = 0; t < 4; t++) {
                uint32_t bh[2], blo[2];
                uint32_t boff = SMEM_SWIZZLE_128B(((uint32_t)(ch * 32 + t * 8) + b_row_l) * 128 +
                                                  (uint32_t)(ks * 2 + b_sel) * 16);
                ldm_x2(bh,  sb + LW_H + boff);
                ldm_x2(blo, sb + LW_L + boff);
                mma_bf16(acc[t], ah, bh);
                mma_bf16(acc[t], ah, blo);
                mma_bf16(acc[t], al, bh);
            }
        }
        // epilogue: relu + bias, split to bf16 hi/lo into A2
        int r0 = rg + (lane >> 2);
        int r1 = r0 + 8;
#pragma unroll
        for (int t = 0; t < 4; t++) {
            int c = ch * 32 + t * 8 + 2 * (lane & 3);
            float2 bb = *(const float2*)(lin_b + c);
            float o0x = fmaxf(acc[t][0] + bb.x, 0.f);
            float o0y = fmaxf(acc[t][1] + bb.y, 0.f);
            float o1x = fmaxf(acc[t][2] + bb.x, 0.f);
            float o1y = fmaxf(acc[t][3] + bb.y, 0.f);
            uint32_t hp, lp;
            split2(o0x, o0y, hp, lp);
            uint32_t off0 = SMEM_SWIZZLE_128B((uint32_t)r0 * 128 + (uint32_t)c * 2);
            *(uint32_t*)(smem + A2_H + off0) = hp;
            *(uint32_t*)(smem + A2_L + off0) = lp;
            split2(o1x, o1y, hp, lp);
            uint32_t off1 = SMEM_SWIZZLE_128B((uint32_t)r1 * 128 + (uint32_t)c * 2);
            *(uint32_t*)(smem + A2_H + off1) = hp;
            *(uint32_t*)(smem + A2_L + off1) = lp;
        }
    }
    __syncthreads();

    // ---- phase 2: xl/xr. warps 0-7 -> xl rows (w)*16; warps 8-15 -> xr ----
    {
        int side = wid >> 3;
        int rg   = (wid & 7) * 16;
        const int B_H = side ? BR_H : BL_H;
        const int B_L = side ? BR_L : BL_L;
        const float* bias = side ? br : bl;
        float* C = side ? xr : xl;

        float acc[16][4];
#pragma unroll
        for (int t = 0; t < 16; t++) {
            acc[t][0] = 0.f; acc[t][1] = 0.f; acc[t][2] = 0.f; acc[t][3] = 0.f;
        }
        uint32_t a_row = (uint32_t)(rg + (lane & 15));
#pragma unroll
        for (int ks = 0; ks < 4; ks++) {
            uint32_t ah[4], al[4];
            uint32_t aoff = SMEM_SWIZZLE_128B(a_row * 128 + (uint32_t)(ks * 2 + a_sel) * 16);
            ldm_x4(ah, sb + A2_H + aoff);
            ldm_x4(al, sb + A2_L + aoff);
#pragma unroll
            for (int t = 0; t < 16; t++) {
                uint32_t bh[2], blo[2];
                uint32_t boff = SMEM_SWIZZLE_128B(((uint32_t)(t * 8) + b_row_l) * 128 +
                                                  (uint32_t)(ks * 2 + b_sel) * 16);
                ldm_x2(bh,  sb + B_H + boff);
                ldm_x2(blo, sb + B_L + boff);
                mma_bf16(acc[t], ah, bh);
                mma_bf16(acc[t], ah, blo);
                mma_bf16(acc[t], al, bh);
            }
        }
        int r0 = n0 + rg + (lane >> 2);
        int r1 = r0 + 8;
#pragma unroll
        for (int t = 0; t < 16; t++) {
            int c = t * 8 + 2 * (lane & 3);
            float2 bb = *(const float2*)(bias + c);
            float2 o0 = make_float2(acc[t][0] + bb.x, acc[t][1] + bb.y);
            float2 o1 = make_float2(acc[t][2] + bb.x, acc[t][3] + bb.y);
            if (r0 < NN) *(float2*)(C + (size_t)r0 * 128 + c) = o0;
            if (r1 < NN) *(float2*)(C + (size_t)r1 * 128 + c) = o1;
        }
    }
}

// ---------------- readout GEMM (mma.sync, same as validated round-12 kernel) ----------------
template<int KOUT, bool RELU>
__global__ void __launch_bounds__(256) gemmM_k(
    const float* __restrict__ A, const float* __restrict__ W,
    const float* __restrict__ bias, float* __restrict__ C) {
    extern __shared__ __align__(1024) char smem[];
    const int SM_AH = 0;
    const int SM_AL = 16384;
    const int SM_BH = 32768;
    const int SM_BL = 32768 + KOUT * 128;
    constexpr int NT = KOUT / 8;

    uint32_t sb = smem_to_u32(smem);
    int tid  = threadIdx.x;
    int wid  = tid >> 5;
    int lane = tid & 31;
    int n0   = blockIdx.x * 128;

    {
        int n    = tid & 127;
        int half = tid >> 7;
        bool valid = (n0 + n) < NN;
        const float4* ar = (const float4*)(A + (size_t)(n0 + n) * 64);
        uint32_t rowoff = (uint32_t)n * 128;
#pragma unroll
        for (int q = half * 8; q < half * 8 + 8; q += 2) {
            float4 f0 = valid ? __ldg(ar + q)     : make_float4(0.f, 0.f, 0.f, 0.f);
            float4 f1 = valid ? __ldg(ar + q + 1) : make_float4(0.f, 0.f, 0.f, 0.f);
            uint32_t h0, l0, h1, l1, h2, l2, h3, l3;
            split2(f0.x, f0.y, h0, l0);
            split2(f0.z, f0.w, h1, l1);
            split2(f1.x, f1.y, h2, l2);
            split2(f1.z, f1.w, h3, l3);
            uint32_t off = SMEM_SWIZZLE_128B(rowoff + (uint32_t)q * 8);
            *(uint4*)(smem + SM_AH + off) = make_uint4(h0, h1, h2, h3);
            *(uint4*)(smem + SM_AL + off) = make_uint4(l0, l1, l2, l3);
        }
    }
    {
        constexpr int NPAIRS = 32 * KOUT;
#pragma unroll
        for (int pf = tid; pf < NPAIRS; pf += 256) {
            int j2 = pf / KOUT;
            int c  = pf % KOUT;
            float w0 = __ldg(W + (size_t)(2 * j2)     * KOUT + c);
            float w1 = __ldg(W + (size_t)(2 * j2 + 1) * KOUT + c);
            uint32_t hp, lp;
            split2(w0, w1, hp, lp);
            uint32_t off = SMEM_SWIZZLE_128B((uint32_t)c * 128 + (uint32_t)j2 * 4);
            *(uint32_t*)(smem + SM_BH + off) = hp;
            *(uint32_t*)(smem + SM_BL + off) = lp;
        }
    }
    __syncthreads();

    float acc[NT][4];
#pragma unroll
    for (int t = 0; t < NT; t++) {
        acc[t][0] = 0.f; acc[t][1] = 0.f; acc[t][2] = 0.f; acc[t][3] = 0.f;
    }
    uint32_t a_row   = (uint32_t)(wid * 16 + (lane & 15));
    uint32_t a_sel   = (uint32_t)(lane >> 4);
    uint32_t b_row_l = (uint32_t)(lane & 7);
    uint32_t b_sel   = (uint32_t)((lane >> 3) & 1);

#pragma unroll
    for (int ks = 0; ks < 4; ks++) {
        uint32_t ah[4], al[4];
        uint32_t aoff = SMEM_SWIZZLE_128B(a_row * 128 + (uint32_t)(ks * 2 + a_sel) * 16);
        ldm_x4(ah, sb + SM_AH + aoff);
        ldm_x4(al, sb + SM_AL + aoff);
#pragma unroll
        for (int t = 0; t < NT; t++) {
            uint32_t bh[2], bl[2];
            uint32_t boff = SMEM_SWIZZLE_128B(((uint32_t)(t * 8) + b_row_l) * 128 +
                                              (uint32_t)(ks * 2 + b_sel) * 16);
            ldm_x2(bh, sb + SM_BH + boff);
            ldm_x2(bl, sb + SM_BL + boff);
            mma_bf16(acc[t], ah, bh);
            mma_bf16(acc[t], ah, bl);
            mma_bf16(acc[t], al, bh);
        }
    }
    {
        int r0 = n0 + wid * 16 + (lane >> 2);
        int r1 = r0 + 8;
#pragma unroll
        for (int t = 0; t < NT; t++) {
            int c = t * 8 + 2 * (lane & 3);
            float2 bb = *(const float2*)(bias + c);
            float2 o0 = make_float2(acc[t][0] + bb.x, acc[t][1] + bb.y);
            float2 o1 = make_float2(acc[t][2] + bb.x, acc[t][3] + bb.y);
            if (RELU) {
                o0.x = fmaxf(o0.x, 0.f); o0.y = fmaxf(o0.y, 0.f);
                o1.x = fmaxf(o1.x, 0.f); o1.y = fmaxf(o1.y, 0.f);
            }
            if (r0 < NN) *(float2*)(C + (size_t)r0 * KOUT + c) = o0;
            if (r1 < NN) *(float2*)(C + (size_t)r1 * KOUT + c) = o1;
        }
    }
}

// ---------------- GATv2: one warp per dst, 4-edge batched online softmax ----------------
__global__ void gat_k(const float* __restrict__ xl, const float* __restrict__ xr,
                      const float* __restrict__ att, const float* __restrict__ bias,
                      float* __restrict__ hout) {
    int gw = (blockIdx.x * blockDim.x + threadIdx.x) >> 5;
    if (gw >= NN) return;
    int lane = threadIdx.x & 31;
    int dst = gw;

    float4 xr4 = *(const float4*)(xr + dst * 128 + lane * 4);
    float4 at4 = *(const float4*)(att + lane * 4);

    int beg = __ldg(g_rowoff + dst), end = __ldg(g_rowoff + dst + 1);

    float m = -1e30f, s = 0.f;
    float ax = 0.f, ay = 0.f, az = 0.f, aw = 0.f;

    for (int i = beg; i < end; i += 4) {
        float p[4];
        float4 xs[4];
#pragma unroll
        for (int k = 0; k < 4; k++) {
            bool valid = (i + k) < end;
            int src = valid ? __ldg(g_csrsrc + i + k) : 0;
            xs[k] = __ldg((const float4*)(xl + src * 128 + lane * 4));
            float vx = xs[k].x + xr4.x, vy = xs[k].y + xr4.y;
            float vz = xs[k].z + xr4.z, vw = xs[k].w + xr4.w;
            vx = vx > 0.f ? vx : 0.2f * vx;
            vy = vy > 0.f ? vy : 0.2f * vy;
            vz = vz > 0.f ? vz : 0.2f * vz;
            vw = vw > 0.f ? vw : 0.2f * vw;
            float pk = vx * at4.x + vy * at4.y + vz * at4.z + vw * at4.w;
            p[k] = valid ? pk : -1e30f;
        }
#pragma unroll
        for (int k = 0; k < 4; k++) {
            float pk = p[k];
            pk += __shfl_xor_sync(0xffffffffu, pk, 1);
            pk += __shfl_xor_sync(0xffffffffu, pk, 2);
            pk += __shfl_xor_sync(0xffffffffu, pk, 4);
            pk += __shfl_xor_sync(0xffffffffu, pk, 8);
            p[k] = ((i + k) < end) ? pk : -1e30f;
        }
        float mb = fmaxf(fmaxf(p[0], p[1]), fmaxf(p[2], p[3]));
        float mn = fmaxf(m, mb);
        float r  = __expf(m - mn);
        float w0 = __expf(p[0] - mn);
        float w1 = __expf(p[1] - mn);
        float w2 = __expf(p[2] - mn);
        float w3 = __expf(p[3] - mn);
        s  = s * r + ((w0 + w1) + (w2 + w3));
        ax = ax * r + w0 * xs[0].x + w1 * xs[1].x + w2 * xs[2].x + w3 * xs[3].x;
        ay = ay * r + w0 * xs[0].y + w1 * xs[1].y + w2 * xs[2].y + w3 * xs[3].y;
        az = az * r + w0 * xs[0].z + w1 * xs[1].z + w2 * xs[2].z + w3 * xs[3].z;
        aw = aw * r + w0 * xs[0].w + w1 * xs[1].w + w2 * xs[2].w + w3 * xs[3].w;
        m = mn;
    }

    float inv = 1.f / s;
    ax *= inv; ay *= inv; az *= inv; aw *= inv;

    float bx = ax + __shfl_xor_sync(0xffffffffu, ax, 16);
    float by = ay + __shfl_xor_sync(0xffffffffu, ay, 16);
    float bz = az + __shfl_xor_sync(0xffffffffu, az, 16);
    float bw = aw + __shfl_xor_sync(0xffffffffu, aw, 16);

    if (lane < 16) {
        float4 b4 = *(const float4*)(bias + lane * 4);
        float4 o = make_float4(0.5f * bx + b4.x, 0.5f * by + b4.y,
                               0.5f * bz + b4.z, 0.5f * bw + b4.w);
        *(float4*)(hout + dst * 64 + lane * 4) = o;
    }
}

// ---------------- output zero + graph segment-sum ----------------
__global__ void zero_k(float* __restrict__ out) {
    int t = blockIdx.x * blockDim.x + threadIdx.x;
    if (t < GG * 128 / 4)
        *(float4*)(out + t * 4) = make_float4(0.f, 0.f, 0.f, 0.f);
}

__global__ void segsum_k(const int* __restrict__ batch, const float* __restrict__ outn,
                         float* __restrict__ out) {
    int t = blockIdx.x * blockDim.x + threadIdx.x;
    if (t >= NN * 32) return;
    int n = t >> 5, q = t & 31;
    float4 v = *(const float4*)(outn + n * 128 + q * 4);
    int g = batch[n];
    float* p = out + g * 128 + q * 4;
    atomicAdd(p + 0, v.x);
    atomicAdd(p + 1, v.y);
    atomicAdd(p + 2, v.z);
    atomicAdd(p + 3, v.w);
}

// ---------------- launcher ----------------
extern "C" void kernel_launch(void* const* d_in, const int* in_sizes, int n_in,
                              void* d_out, int out_size) {
    const int* x     = (const int*)d_in[0];
    const int* ei    = (const int*)d_in[1];
    const int* batch = (const int*)d_in[2];
    int base = (in_sizes[3] == 1) ? 4 : 3;
    const float* embed = (const float*)d_in[base + 0];
    const float* lin_W = (const float*)d_in[base + 1];
    const float* lin_b = (const float*)d_in[base + 2];
    const float* gWl   = (const float*)d_in[base + 3];
    const float* gbl   = (const float*)d_in[base + 4];
    const float* gWr   = (const float*)d_in[base + 5];
    const float* gbr   = (const float*)d_in[base + 6];
    const float* gatt  = (const float*)d_in[base + 7];
    const float* gbias = (const float*)d_in[base + 8];
    const float* rW    = (const float*)d_in[base + 9];
    const float* rb    = (const float*)d_in[base + 10];
    float* out = (float*)d_out;

    void* ph  = 0;
    void* pxl = 0;
    void* pxr = 0;
    cudaGetSymbolAddress(&ph,  g_h);
    cudaGetSymbolAddress(&pxl, g_xl);
    cudaGetSymbolAddress(&pxr, g_xr);
    float* h  = (float*)ph;
    float* xl = (float*)pxl;
    float* xr = (float*)pxr;

    const int SMEM_FUSED = 147456;                 // 144KB
    const int SMEM128    = 32768 + 128 * 256;      // 65536
    cudaFuncSetAttribute(fused_layer_k, cudaFuncAttributeMaxDynamicSharedMemorySize, SMEM_FUSED);
    cudaFuncSetAttribute(gemmM_k<128, false>, cudaFuncAttributeMaxDynamicSharedMemorySize, SMEM128);

    // launches 1-3 (blocksum after hist; keeps fused kernel in ncu capture slot 4)
    embed_k<<<(NN * 16 + 255) / 256, 256>>>(x, embed);   // also inits g_deg
    hist_k<<<(EE + 255) / 256, 256>>>(ei);
    blocksum_k<<<NBLK, 256>>>();

    // launch 4 = fused layer 0 (capture slot)
    fused_layer_k<<<GTB, 512, SMEM_FUSED>>>(h, lin_W, lin_b, gWl, gbl, gWr, gbr, xl, xr);

    // finish CSR build (needed only by gat_k)
    bscan_k<<<1, 256>>>();
    scatter_scan_k<<<NBLK, 256>>>();
    fill_k<<<(EN + 255) / 256, 256>>>(ei);

    gat_k<<<(NN + 7) / 8, 256>>>(xl, xr, gatt, gbias, h);

    for (int l = 1; l < 3; l++) {
        fused_layer_k<<<GTB, 512, SMEM_FUSED>>>(h, lin_W + l * 64 * 64, lin_b + l * 64,
                                                gWl + l * 64 * 128, gbl + l * 128,
                                                gWr + l * 64 * 128, gbr + l * 128, xl, xr);
        gat_k<<<(NN + 7) / 8, 256>>>(xl, xr, gatt + l * 128, gbias + l * 64, h);
    }

    gemmM_k<128, false><<<GTB, 256, SMEM128>>>(h, rW, rb, xl);
    zero_k<<<(GG * 128 / 4 + 255) / 256, 256>>>(out);
    segsum_k<<<(NN * 32 + 255) / 256, 256>>>(batch, xl, out);
}